// round 1
// baseline (speedup 1.0000x reference)
#include <cuda_runtime.h>
#include <cstdint>

#define BB 4
#define SS 2048
#define HH 1024
#define NHH 16
#define HDD 64
#define BH (BB*NHH)   // 64 heads total

// Head-major scratch: [B*NH][S][HD]
__device__ float g_q[BB*SS*HH];
__device__ float g_k[BB*SS*HH];
__device__ float g_v[BB*SS*HH];

__device__ __forceinline__ float tf32r(float x) {
    uint32_t r;
    asm("cvt.rna.tf32.f32 %0, %1;" : "=r"(r) : "f"(x));
    return __uint_as_float(r);
}
__device__ __forceinline__ uint32_t fb(float x) { return __float_as_uint(x); }

__device__ __forceinline__ void mma8(float c[4],
                                     uint32_t a0, uint32_t a1, uint32_t a2, uint32_t a3,
                                     uint32_t b0, uint32_t b1) {
    asm volatile(
        "mma.sync.aligned.m16n8k8.row.col.f32.tf32.tf32.f32 "
        "{%0,%1,%2,%3},{%4,%5,%6,%7},{%8,%9},{%0,%1,%2,%3};\n"
        : "+f"(c[0]), "+f"(c[1]), "+f"(c[2]), "+f"(c[3])
        : "r"(a0), "r"(a1), "r"(a2), "r"(a3), "r"(b0), "r"(b1));
}

// ======================= QKV projection GEMM =======================
// C[m][n] = sum_k X[m][k] * W[n][k] + bias[n]  (X: [8192,1024], W: [1024,1024])
// Output scattered to head-major scratch.
// CTA tile 128x128x32, 8 warps (2x4), warp tile 64x32 = 4x4 m16n8 tiles.
__global__ __launch_bounds__(256) void qkv_gemm_kernel(
    const float* __restrict__ X,
    const float* __restrict__ Wq, const float* __restrict__ bq,
    const float* __restrict__ Wk, const float* __restrict__ bk,
    const float* __restrict__ Wv, const float* __restrict__ bv)
{
    __shared__ float As[128 * 36];
    __shared__ float Bs[128 * 36];

    const float* W; const float* bias; float* out;
    if (blockIdx.z == 0)      { W = Wq; bias = bq; out = g_q; }
    else if (blockIdx.z == 1) { W = Wk; bias = bk; out = g_k; }
    else                      { W = Wv; bias = bv; out = g_v; }

    const int m0 = blockIdx.x * 128;
    const int n0 = blockIdx.y * 128;
    const int tid = threadIdx.x;
    const int lane = tid & 31, warp = tid >> 5;
    const int wm = warp >> 2, wn = warp & 3;     // 2 x 4 warp grid
    const int g = lane >> 2, tg = lane & 3;

    float acc[4][4][4];
    #pragma unroll
    for (int mt = 0; mt < 4; mt++)
        #pragma unroll
        for (int nt = 0; nt < 4; nt++)
            #pragma unroll
            for (int j = 0; j < 4; j++) acc[mt][nt][j] = 0.f;

    for (int k0 = 0; k0 < HH; k0 += 32) {
        // Load A (X) and B (W) 128x32 tiles, convert to tf32, padded stride 36
        #pragma unroll
        for (int i = 0; i < 4; i++) {
            int idx = tid + i * 256;             // 0..1023 float4s
            int row = idx >> 3;
            int c4  = (idx & 7) * 4;
            float4 va = *(const float4*)&X[(size_t)(m0 + row) * HH + k0 + c4];
            float* da = &As[row * 36 + c4];
            da[0] = tf32r(va.x); da[1] = tf32r(va.y); da[2] = tf32r(va.z); da[3] = tf32r(va.w);
            float4 vb = *(const float4*)&W[(size_t)(n0 + row) * HH + k0 + c4];
            float* db = &Bs[row * 36 + c4];
            db[0] = tf32r(vb.x); db[1] = tf32r(vb.y); db[2] = tf32r(vb.z); db[3] = tf32r(vb.w);
        }
        __syncthreads();

        #pragma unroll
        for (int ks = 0; ks < 4; ks++) {
            uint32_t a[4][4];
            #pragma unroll
            for (int mt = 0; mt < 4; mt++) {
                int r = wm * 64 + mt * 16 + g;
                a[mt][0] = fb(As[r * 36 + ks * 8 + tg]);
                a[mt][1] = fb(As[(r + 8) * 36 + ks * 8 + tg]);
                a[mt][2] = fb(As[r * 36 + ks * 8 + tg + 4]);
                a[mt][3] = fb(As[(r + 8) * 36 + ks * 8 + tg + 4]);
            }
            #pragma unroll
            for (int nt = 0; nt < 4; nt++) {
                int n = wn * 32 + nt * 8 + g;
                uint32_t b0 = fb(Bs[n * 36 + ks * 8 + tg]);
                uint32_t b1 = fb(Bs[n * 36 + ks * 8 + tg + 4]);
                #pragma unroll
                for (int mt = 0; mt < 4; mt++)
                    mma8(acc[mt][nt], a[mt][0], a[mt][1], a[mt][2], a[mt][3], b0, b1);
            }
        }
        __syncthreads();
    }

    // Epilogue: bias + scatter to head-major [B*NH][S][HD]
    #pragma unroll
    for (int mt = 0; mt < 4; mt++) {
        int r = m0 + wm * 64 + mt * 16 + g;
        int b_  = r >> 11, s_ = r & 2047;
        int b8_ = (r + 8) >> 11, s8_ = (r + 8) & 2047;   // r+8 within same 2048 block (tile-aligned)
        #pragma unroll
        for (int nt = 0; nt < 4; nt++) {
            int c = n0 + wn * 32 + nt * 8 + 2 * tg;
            int nh = c >> 6, hd = c & 63;
            float bi0 = bias[c], bi1 = bias[c + 1];
            int base0 = (((b_  << 4) + nh) * SS + s_ ) * HDD + hd;
            int base8 = (((b8_ << 4) + nh) * SS + s8_) * HDD + hd;
            out[base0]     = acc[mt][nt][0] + bi0;
            out[base0 + 1] = acc[mt][nt][1] + bi1;
            out[base8]     = acc[mt][nt][2] + bi0;
            out[base8 + 1] = acc[mt][nt][3] + bi1;
        }
    }
}

// ======================= Flash attention =======================
// One CTA per (head, 64-query tile). 4 warps, each owns 16 query rows.
// Loop over 32 key tiles of 64: S = Q K^T (mma), online softmax, O += P V (mma).
#define SMSTRIDE 68
#define ATTN_SMEM ((4 * 64 * SMSTRIDE + 64) * (int)sizeof(float))

__global__ __launch_bounds__(128) void attn_kernel(const float* __restrict__ mask,
                                                   float* __restrict__ out)
{
    extern __shared__ float sm[];
    float* Qs = sm;
    float* Ks = Qs + 64 * SMSTRIDE;
    float* Vs = Ks + 64 * SMSTRIDE;
    float* Ps = Vs + 64 * SMSTRIDE;
    float* Ms = Ps + 64 * SMSTRIDE;

    const int tid = threadIdx.x;
    const int lane = tid & 31, warp = tid >> 5;
    const int g = lane >> 2, tg = lane & 3;
    const int hbh = blockIdx.y;            // 0..63
    const int b = hbh >> 4, nh = hbh & 15;
    const int q0 = blockIdx.x * 64;
    const int r0 = warp * 16;

    const float* qb = g_q + ((size_t)hbh * SS + q0) * HDD;
    const float* kb = g_k + (size_t)hbh * SS * HDD;
    const float* vb = g_v + (size_t)hbh * SS * HDD;

    // Load Q tile, pre-scaled by 1/sqrt(HD)=0.125, tf32-rounded
    #pragma unroll
    for (int i = 0; i < 8; i++) {
        int idx = tid + i * 128;           // 0..1023 float4s
        int row = idx >> 4;
        int c4 = (idx & 15) * 4;
        float4 v = *(const float4*)&qb[row * 64 + c4];
        float* d = &Qs[row * SMSTRIDE + c4];
        d[0] = tf32r(v.x * 0.125f); d[1] = tf32r(v.y * 0.125f);
        d[2] = tf32r(v.z * 0.125f); d[3] = tf32r(v.w * 0.125f);
    }

    float O[8][4];
    #pragma unroll
    for (int nt = 0; nt < 8; nt++)
        #pragma unroll
        for (int j = 0; j < 4; j++) O[nt][j] = 0.f;
    float m0s = -1e30f, m1s = -1e30f, l0 = 0.f, l1 = 0.f;

    for (int kt = 0; kt < 32; kt++) {
        __syncthreads();   // prior-iter Vs/Ps reads done; also fences Q load on kt=0
        #pragma unroll
        for (int i = 0; i < 8; i++) {
            int idx = tid + i * 128;
            int row = idx >> 4;
            int c4 = (idx & 15) * 4;
            float4 vk = *(const float4*)&kb[(kt * 64 + row) * 64 + c4];
            float* dk = &Ks[row * SMSTRIDE + c4];
            dk[0] = tf32r(vk.x); dk[1] = tf32r(vk.y); dk[2] = tf32r(vk.z); dk[3] = tf32r(vk.w);
            float4 vv = *(const float4*)&vb[(kt * 64 + row) * 64 + c4];
            float* dv = &Vs[row * SMSTRIDE + c4];
            dv[0] = tf32r(vv.x); dv[1] = tf32r(vv.y); dv[2] = tf32r(vv.z); dv[3] = tf32r(vv.w);
        }
        if (tid < 64) Ms[tid] = mask[b * SS + kt * 64 + tid];
        __syncthreads();

        // S = Q K^T  (M=16 q-rows per warp, N=64 keys, K=64 hd)
        float s[8][4];
        #pragma unroll
        for (int nt = 0; nt < 8; nt++)
            #pragma unroll
            for (int j = 0; j < 4; j++) s[nt][j] = 0.f;

        #pragma unroll
        for (int ks = 0; ks < 8; ks++) {
            uint32_t a0 = fb(Qs[(r0 + g) * SMSTRIDE + ks * 8 + tg]);
            uint32_t a1 = fb(Qs[(r0 + 8 + g) * SMSTRIDE + ks * 8 + tg]);
            uint32_t a2 = fb(Qs[(r0 + g) * SMSTRIDE + ks * 8 + tg + 4]);
            uint32_t a3 = fb(Qs[(r0 + 8 + g) * SMSTRIDE + ks * 8 + tg + 4]);
            #pragma unroll
            for (int nt = 0; nt < 8; nt++) {
                uint32_t b0 = fb(Ks[(nt * 8 + g) * SMSTRIDE + ks * 8 + tg]);
                uint32_t b1 = fb(Ks[(nt * 8 + g) * SMSTRIDE + ks * 8 + tg + 4]);
                mma8(s[nt], a0, a1, a2, a3, b0, b1);
            }
        }

        // mask add + row max (rows g and g+8 of this warp's 16)
        float mx0 = -1e30f, mx1 = -1e30f;
        #pragma unroll
        for (int nt = 0; nt < 8; nt++) {
            float mk0 = Ms[nt * 8 + 2 * tg], mk1 = Ms[nt * 8 + 2 * tg + 1];
            s[nt][0] += mk0; s[nt][1] += mk1; s[nt][2] += mk0; s[nt][3] += mk1;
            mx0 = fmaxf(mx0, fmaxf(s[nt][0], s[nt][1]));
            mx1 = fmaxf(mx1, fmaxf(s[nt][2], s[nt][3]));
        }
        mx0 = fmaxf(mx0, __shfl_xor_sync(0xffffffffu, mx0, 1));
        mx0 = fmaxf(mx0, __shfl_xor_sync(0xffffffffu, mx0, 2));
        mx1 = fmaxf(mx1, __shfl_xor_sync(0xffffffffu, mx1, 1));
        mx1 = fmaxf(mx1, __shfl_xor_sync(0xffffffffu, mx1, 2));

        float mn0 = fmaxf(m0s, mx0), mn1 = fmaxf(m1s, mx1);
        float al0 = __expf(m0s - mn0), al1 = __expf(m1s - mn1);
        m0s = mn0; m1s = mn1;

        float ls0 = 0.f, ls1 = 0.f;
        #pragma unroll
        for (int nt = 0; nt < 8; nt++) {
            float p0 = __expf(s[nt][0] - mn0);
            float p1 = __expf(s[nt][1] - mn0);
            float p2 = __expf(s[nt][2] - mn1);
            float p3 = __expf(s[nt][3] - mn1);
            ls0 += p0 + p1; ls1 += p2 + p3;
            Ps[(r0 + g) * SMSTRIDE + nt * 8 + 2 * tg]         = tf32r(p0);
            Ps[(r0 + g) * SMSTRIDE + nt * 8 + 2 * tg + 1]     = tf32r(p1);
            Ps[(r0 + 8 + g) * SMSTRIDE + nt * 8 + 2 * tg]     = tf32r(p2);
            Ps[(r0 + 8 + g) * SMSTRIDE + nt * 8 + 2 * tg + 1] = tf32r(p3);
        }
        ls0 += __shfl_xor_sync(0xffffffffu, ls0, 1);
        ls0 += __shfl_xor_sync(0xffffffffu, ls0, 2);
        ls1 += __shfl_xor_sync(0xffffffffu, ls1, 1);
        ls1 += __shfl_xor_sync(0xffffffffu, ls1, 2);
        l0 = l0 * al0 + ls0;
        l1 = l1 * al1 + ls1;

        #pragma unroll
        for (int nt = 0; nt < 8; nt++) {
            O[nt][0] *= al0; O[nt][1] *= al0; O[nt][2] *= al1; O[nt][3] *= al1;
        }
        __syncwarp();   // Ps region is per-warp private: warp sync suffices

        // O += P V  (M=16 q-rows, N=64 hd, K=64 keys)
        #pragma unroll
        for (int ks = 0; ks < 8; ks++) {
            uint32_t a0 = fb(Ps[(r0 + g) * SMSTRIDE + ks * 8 + tg]);
            uint32_t a1 = fb(Ps[(r0 + 8 + g) * SMSTRIDE + ks * 8 + tg]);
            uint32_t a2 = fb(Ps[(r0 + g) * SMSTRIDE + ks * 8 + tg + 4]);
            uint32_t a3 = fb(Ps[(r0 + 8 + g) * SMSTRIDE + ks * 8 + tg + 4]);
            #pragma unroll
            for (int nt = 0; nt < 8; nt++) {
                uint32_t b0 = fb(Vs[(ks * 8 + tg) * SMSTRIDE + nt * 8 + g]);
                uint32_t b1 = fb(Vs[(ks * 8 + tg + 4) * SMSTRIDE + nt * 8 + g]);
                mma8(O[nt], a0, a1, a2, a3, b0, b1);
            }
        }
    }

    // Normalize + write to [B,S,H]
    float i0 = 1.f / l0, i1 = 1.f / l1;
    int rg  = q0 + r0 + g;
    int rg8 = rg + 8;
    #pragma unroll
    for (int nt = 0; nt < 8; nt++) {
        int hd = nt * 8 + 2 * tg;
        int o0 = (b * SS + rg ) * HH + nh * 64 + hd;
        int o8 = (b * SS + rg8) * HH + nh * 64 + hd;
        out[o0]     = O[nt][0] * i0;
        out[o0 + 1] = O[nt][1] * i0;
        out[o8]     = O[nt][2] * i1;
        out[o8 + 1] = O[nt][3] * i1;
    }
}

extern "C" void kernel_launch(void* const* d_in, const int* in_sizes, int n_in,
                              void* d_out, int out_size)
{
    const float* X    = (const float*)d_in[0];
    const float* mask = (const float*)d_in[1];
    const float* Wq   = (const float*)d_in[2];
    const float* bq   = (const float*)d_in[3];
    const float* Wk   = (const float*)d_in[4];
    const float* bk   = (const float*)d_in[5];
    const float* Wv   = (const float*)d_in[6];
    const float* bv   = (const float*)d_in[7];
    float* out = (float*)d_out;

    cudaFuncSetAttribute(attn_kernel, cudaFuncAttributeMaxDynamicSharedMemorySize, ATTN_SMEM);

    dim3 gg(8192 / 128, HH / 128, 3);
    qkv_gemm_kernel<<<gg, 256>>>(X, Wq, bq, Wk, bk, Wv, bv);

    dim3 ga(SS / 64, BH);
    attn_kernel<<<ga, 128, ATTN_SMEM>>>(mask, out);
}

// round 2
// speedup vs baseline: 1.2394x; 1.2394x over previous
#include <cuda_runtime.h>
#include <cstdint>

#define BB 4
#define SS 2048
#define HH 1024
#define NHH 16
#define HDD 64
#define BH (BB*NHH)   // 64 heads total

// Scratch: Q,K head-major [B*NH][S][HD]; V transposed [B*NH][HD][S]
__device__ float g_q[BB*SS*HH];
__device__ float g_k[BB*SS*HH];
__device__ float g_v[BB*SS*HH];

__device__ __forceinline__ float tf32r(float x) {
    uint32_t r;
    asm("cvt.rna.tf32.f32 %0, %1;" : "=r"(r) : "f"(x));
    return __uint_as_float(r);
}
__device__ __forceinline__ uint32_t fb(float x) { return __float_as_uint(x); }

__device__ __forceinline__ void mma8(float c[4],
                                     uint32_t a0, uint32_t a1, uint32_t a2, uint32_t a3,
                                     uint32_t b0, uint32_t b1) {
    asm volatile(
        "mma.sync.aligned.m16n8k8.row.col.f32.tf32.tf32.f32 "
        "{%0,%1,%2,%3},{%4,%5,%6,%7},{%8,%9},{%0,%1,%2,%3};\n"
        : "+f"(c[0]), "+f"(c[1]), "+f"(c[2]), "+f"(c[3])
        : "r"(a0), "r"(a1), "r"(a2), "r"(a3), "r"(b0), "r"(b1));
}

// ======================= QKV projection GEMM =======================
// C[m][n] = sum_k X[m][k] * W[n][k] + bias[n]
// Q,K written head-major [head][S][HD]; V written transposed [head][HD][S].
__global__ __launch_bounds__(256) void qkv_gemm_kernel(
    const float* __restrict__ X,
    const float* __restrict__ Wq, const float* __restrict__ bq,
    const float* __restrict__ Wk, const float* __restrict__ bk,
    const float* __restrict__ Wv, const float* __restrict__ bv)
{
    __shared__ float As[128 * 36];
    __shared__ float Bs[128 * 36];

    const float* W; const float* bias; float* out;
    if (blockIdx.z == 0)      { W = Wq; bias = bq; out = g_q; }
    else if (blockIdx.z == 1) { W = Wk; bias = bk; out = g_k; }
    else                      { W = Wv; bias = bv; out = g_v; }
    const bool vtrans = (blockIdx.z == 2);

    const int m0 = blockIdx.x * 128;
    const int n0 = blockIdx.y * 128;
    const int tid = threadIdx.x;
    const int lane = tid & 31, warp = tid >> 5;
    const int wm = warp >> 2, wn = warp & 3;
    const int g = lane >> 2, tg = lane & 3;

    float acc[4][4][4];
    #pragma unroll
    for (int mt = 0; mt < 4; mt++)
        #pragma unroll
        for (int nt = 0; nt < 4; nt++)
            #pragma unroll
            for (int j = 0; j < 4; j++) acc[mt][nt][j] = 0.f;

    for (int k0 = 0; k0 < HH; k0 += 32) {
        #pragma unroll
        for (int i = 0; i < 4; i++) {
            int idx = tid + i * 256;
            int row = idx >> 3;
            int c4  = (idx & 7) * 4;
            float4 va = *(const float4*)&X[(size_t)(m0 + row) * HH + k0 + c4];
            float4 ta = make_float4(tf32r(va.x), tf32r(va.y), tf32r(va.z), tf32r(va.w));
            *(float4*)&As[row * 36 + c4] = ta;
            float4 vb = *(const float4*)&W[(size_t)(n0 + row) * HH + k0 + c4];
            float4 tb = make_float4(tf32r(vb.x), tf32r(vb.y), tf32r(vb.z), tf32r(vb.w));
            *(float4*)&Bs[row * 36 + c4] = tb;
        }
        __syncthreads();

        #pragma unroll
        for (int ks = 0; ks < 4; ks++) {
            uint32_t a[4][4];
            #pragma unroll
            for (int mt = 0; mt < 4; mt++) {
                int r = wm * 64 + mt * 16 + g;
                a[mt][0] = fb(As[r * 36 + ks * 8 + tg]);
                a[mt][1] = fb(As[(r + 8) * 36 + ks * 8 + tg]);
                a[mt][2] = fb(As[r * 36 + ks * 8 + tg + 4]);
                a[mt][3] = fb(As[(r + 8) * 36 + ks * 8 + tg + 4]);
            }
            #pragma unroll
            for (int nt = 0; nt < 4; nt++) {
                int n = wn * 32 + nt * 8 + g;
                uint32_t b0 = fb(Bs[n * 36 + ks * 8 + tg]);
                uint32_t b1 = fb(Bs[n * 36 + ks * 8 + tg + 4]);
                #pragma unroll
                for (int mt = 0; mt < 4; mt++)
                    mma8(acc[mt][nt], a[mt][0], a[mt][1], a[mt][2], a[mt][3], b0, b1);
            }
        }
        __syncthreads();
    }

    // Epilogue: bias + scatter
    #pragma unroll
    for (int mt = 0; mt < 4; mt++) {
        int r = m0 + wm * 64 + mt * 16 + g;
        int b_  = r >> 11, s_ = r & 2047;
        int b8_ = (r + 8) >> 11, s8_ = (r + 8) & 2047;
        #pragma unroll
        for (int nt = 0; nt < 4; nt++) {
            int c = n0 + wn * 32 + nt * 8 + 2 * tg;
            int nh = c >> 6, hd = c & 63;
            float bi0 = bias[c], bi1 = bias[c + 1];
            int h0 = (b_  << 4) + nh;
            int h8 = (b8_ << 4) + nh;
            if (vtrans) {
                // V^T: [head][hd][s]
                int t0 = (h0 * HDD + hd) * SS + s_;
                int t8 = (h8 * HDD + hd) * SS + s8_;
                out[t0]      = acc[mt][nt][0] + bi0;
                out[t0 + SS] = acc[mt][nt][1] + bi1;
                out[t8]      = acc[mt][nt][2] + bi0;
                out[t8 + SS] = acc[mt][nt][3] + bi1;
            } else {
                int base0 = (h0 * SS + s_ ) * HDD + hd;
                int base8 = (h8 * SS + s8_) * HDD + hd;
                out[base0]     = acc[mt][nt][0] + bi0;
                out[base0 + 1] = acc[mt][nt][1] + bi1;
                out[base8]     = acc[mt][nt][2] + bi0;
                out[base8 + 1] = acc[mt][nt][3] + bi1;
            }
        }
    }
}

// ======================= Flash attention =======================
// CTA: 8 warps, 128 query rows (16/warp). K-tile = 64 keys.
// Q fragments live in registers for the whole kernel. P converted to
// A-operand layout via shuffles (no smem round trip). V stored transposed
// so PV B-fragment LDS is conflict-free.
#define KSTR 68

__global__ __launch_bounds__(256, 2) void attn_kernel(const float* __restrict__ mask,
                                                      float* __restrict__ out)
{
    __shared__ float Ks[64 * KSTR];
    __shared__ float Vt[64 * KSTR];   // V^T tile: [hd][key]
    __shared__ float Ms[64];

    const int tid = threadIdx.x;
    const int lane = tid & 31, warp = tid >> 5;
    const int g = lane >> 2, tg = lane & 3;
    const int hbh = blockIdx.y;            // 0..63
    const int b = hbh >> 4, nh = hbh & 15;
    const int q0 = blockIdx.x * 128;
    const int r0 = warp * 16;

    const float* qb  = g_q + ((size_t)hbh * SS + q0) * HDD;
    const float* kb  = g_k + (size_t)hbh * SS * HDD;
    const float* vtb = g_v + (size_t)hbh * HDD * SS;

    // Q fragments -> registers, pre-scaled by 1/sqrt(HD), tf32-rounded
    uint32_t qa[8][4];
    #pragma unroll
    for (int ks = 0; ks < 8; ks++) {
        qa[ks][0] = fb(tf32r(qb[(r0 + g)     * 64 + ks * 8 + tg]     * 0.125f));
        qa[ks][1] = fb(tf32r(qb[(r0 + 8 + g) * 64 + ks * 8 + tg]     * 0.125f));
        qa[ks][2] = fb(tf32r(qb[(r0 + g)     * 64 + ks * 8 + tg + 4] * 0.125f));
        qa[ks][3] = fb(tf32r(qb[(r0 + 8 + g) * 64 + ks * 8 + tg + 4] * 0.125f));
    }

    float O[8][4];
    #pragma unroll
    for (int nt = 0; nt < 8; nt++)
        #pragma unroll
        for (int j = 0; j < 4; j++) O[nt][j] = 0.f;
    float m0s = -1e30f, m1s = -1e30f, l0 = 0.f, l1 = 0.f;

    const int srcA = (lane & ~3) | (tg >> 1);
    const int srcB = srcA + 2;
    const bool odd = (tg & 1);

    for (int kt = 0; kt < 32; kt++) {
        __syncthreads();
        // Fill K tile [key][hd] and V^T tile [hd][key]
        #pragma unroll
        for (int i = 0; i < 4; i++) {
            int idx = tid + i * 256;       // 0..1023 float4s
            int row = idx >> 4;
            int c4 = (idx & 15) * 4;
            float4 vk = *(const float4*)&kb[(kt * 64 + row) * 64 + c4];
            *(float4*)&Ks[row * KSTR + c4] =
                make_float4(tf32r(vk.x), tf32r(vk.y), tf32r(vk.z), tf32r(vk.w));
            float4 vv = *(const float4*)&vtb[(size_t)row * SS + kt * 64 + c4];
            *(float4*)&Vt[row * KSTR + c4] =
                make_float4(tf32r(vv.x), tf32r(vv.y), tf32r(vv.z), tf32r(vv.w));
        }
        if (tid < 64) Ms[tid] = mask[b * SS + kt * 64 + tid];
        __syncthreads();

        // S = Q K^T
        float s[8][4];
        #pragma unroll
        for (int nt = 0; nt < 8; nt++)
            #pragma unroll
            for (int j = 0; j < 4; j++) s[nt][j] = 0.f;

        #pragma unroll
        for (int ks = 0; ks < 8; ks++) {
            #pragma unroll
            for (int nt = 0; nt < 8; nt++) {
                uint32_t b0 = fb(Ks[(nt * 8 + g) * KSTR + ks * 8 + tg]);
                uint32_t b1 = fb(Ks[(nt * 8 + g) * KSTR + ks * 8 + tg + 4]);
                mma8(s[nt], qa[ks][0], qa[ks][1], qa[ks][2], qa[ks][3], b0, b1);
            }
        }

        // mask + row max
        float mx0 = -1e30f, mx1 = -1e30f;
        #pragma unroll
        for (int nt = 0; nt < 8; nt++) {
            float mk0 = Ms[nt * 8 + 2 * tg], mk1 = Ms[nt * 8 + 2 * tg + 1];
            s[nt][0] += mk0; s[nt][1] += mk1; s[nt][2] += mk0; s[nt][3] += mk1;
            mx0 = fmaxf(mx0, fmaxf(s[nt][0], s[nt][1]));
            mx1 = fmaxf(mx1, fmaxf(s[nt][2], s[nt][3]));
        }
        mx0 = fmaxf(mx0, __shfl_xor_sync(0xffffffffu, mx0, 1));
        mx0 = fmaxf(mx0, __shfl_xor_sync(0xffffffffu, mx0, 2));
        mx1 = fmaxf(mx1, __shfl_xor_sync(0xffffffffu, mx1, 1));
        mx1 = fmaxf(mx1, __shfl_xor_sync(0xffffffffu, mx1, 2));

        float mn0 = fmaxf(m0s, mx0), mn1 = fmaxf(m1s, mx1);
        float al0 = __expf(m0s - mn0), al1 = __expf(m1s - mn1);
        m0s = mn0; m1s = mn1;

        float ls0 = 0.f, ls1 = 0.f;
        #pragma unroll
        for (int nt = 0; nt < 8; nt++) {
            float p0 = __expf(s[nt][0] - mn0);
            float p1 = __expf(s[nt][1] - mn0);
            float p2 = __expf(s[nt][2] - mn1);
            float p3 = __expf(s[nt][3] - mn1);
            ls0 += p0 + p1; ls1 += p2 + p3;
            s[nt][0] = tf32r(p0); s[nt][1] = tf32r(p1);
            s[nt][2] = tf32r(p2); s[nt][3] = tf32r(p3);
        }
        ls0 += __shfl_xor_sync(0xffffffffu, ls0, 1);
        ls0 += __shfl_xor_sync(0xffffffffu, ls0, 2);
        ls1 += __shfl_xor_sync(0xffffffffu, ls1, 1);
        ls1 += __shfl_xor_sync(0xffffffffu, ls1, 2);
        l0 = l0 * al0 + ls0;
        l1 = l1 * al1 + ls1;

        #pragma unroll
        for (int nt = 0; nt < 8; nt++) {
            O[nt][0] *= al0; O[nt][1] *= al0; O[nt][2] *= al1; O[nt][3] *= al1;
        }

        // O += P V : convert P accumulator-layout -> A-operand layout via shfl
        #pragma unroll
        for (int ks = 0; ks < 8; ks++) {
            float x0 = __shfl_sync(0xffffffffu, s[ks][0], srcA);
            float x1 = __shfl_sync(0xffffffffu, s[ks][1], srcA);
            float y0 = __shfl_sync(0xffffffffu, s[ks][0], srcB);
            float y1 = __shfl_sync(0xffffffffu, s[ks][1], srcB);
            float z0 = __shfl_sync(0xffffffffu, s[ks][2], srcA);
            float z1 = __shfl_sync(0xffffffffu, s[ks][3], srcA);
            float w0 = __shfl_sync(0xffffffffu, s[ks][2], srcB);
            float w1 = __shfl_sync(0xffffffffu, s[ks][3], srcB);
            uint32_t a0 = fb(odd ? x1 : x0);
            uint32_t a2 = fb(odd ? y1 : y0);
            uint32_t a1 = fb(odd ? z1 : z0);
            uint32_t a3 = fb(odd ? w1 : w0);
            #pragma unroll
            for (int nt = 0; nt < 8; nt++) {
                uint32_t b0 = fb(Vt[(nt * 8 + g) * KSTR + ks * 8 + tg]);
                uint32_t b1 = fb(Vt[(nt * 8 + g) * KSTR + ks * 8 + tg + 4]);
                mma8(O[nt], a0, a1, a2, a3, b0, b1);
            }
        }
    }

    // Normalize + write [B,S,H]
    float i0 = 1.f / l0, i1 = 1.f / l1;
    int rg  = q0 + r0 + g;
    int rg8 = rg + 8;
    #pragma unroll
    for (int nt = 0; nt < 8; nt++) {
        int hd = nt * 8 + 2 * tg;
        int o0 = (b * SS + rg ) * HH + nh * 64 + hd;
        int o8 = (b * SS + rg8) * HH + nh * 64 + hd;
        out[o0]     = O[nt][0] * i0;
        out[o0 + 1] = O[nt][1] * i0;
        out[o8]     = O[nt][2] * i1;
        out[o8 + 1] = O[nt][3] * i1;
    }
}

extern "C" void kernel_launch(void* const* d_in, const int* in_sizes, int n_in,
                              void* d_out, int out_size)
{
    const float* X    = (const float*)d_in[0];
    const float* mask = (const float*)d_in[1];
    const float* Wq   = (const float*)d_in[2];
    const float* bq   = (const float*)d_in[3];
    const float* Wk   = (const float*)d_in[4];
    const float* bk   = (const float*)d_in[5];
    const float* Wv   = (const float*)d_in[6];
    const float* bv   = (const float*)d_in[7];
    float* out = (float*)d_out;

    dim3 gg(8192 / 128, HH / 128, 3);
    qkv_gemm_kernel<<<gg, 256>>>(X, Wq, bq, Wk, bk, Wv, bv);

    dim3 ga(SS / 128, BH);
    attn_kernel<<<ga, 256>>>(mask, out);
}